// round 3
// baseline (speedup 1.0000x reference)
#include <cuda_runtime.h>

#define NSB 8          // 4 quadrants * B=2
#define NH 8           // heads
#define SHW 128        // sub image H=W
#define SPIX (SHW*SHW) // 16384

// scratch (device globals: allocation-free)
__device__ float g_q[NSB*NH*SPIX];
__device__ float g_k[NSB*NH*SPIX];
__device__ float g_v[NSB*NH*SPIX];
__device__ float g_fx[NSB*SPIX];   // horizontal flow (pixel units)
__device__ float g_fy[NSB*SPIX];   // vertical flow

__device__ __forceinline__ float ex2(float x){
    float r; asm("ex2.approx.ftz.f32 %0, %1;" : "=f"(r) : "f"(x)); return r;
}

// ---------------------------------------------------------------------------
// Kernel 1: fused q/k/v 1x1-conv projection.
// One thread computes ONE (b, row-parity, h, w) and serves TWO subs at once
// (even/odd column) so cur/ref loads are float2 and weight LDS is amortized.
// sub index order (from reference split): 0=ul(0,0) 1=br(1,1) 2=ur(0,1) 3=bl(1,0)
// sb = s*2 + b
// ---------------------------------------------------------------------------
__global__ void __launch_bounds__(256) qkv_kernel(
    const float* __restrict__ cur, const float* __restrict__ ref,
    const float* __restrict__ Wq, const float* __restrict__ Wk,
    const float* __restrict__ Wv)
{
    __shared__ float sW[1536];   // Wq | Wk | Wv, each [8][64]
    for (int i = threadIdx.x; i < 1536; i += 256)
        sW[i] = (i < 512) ? Wq[i] : (i < 1024 ? Wk[i-512] : Wv[i-1024]);
    __syncthreads();

    int t = blockIdx.x*256 + threadIdx.x;          // 65536 threads total
    int w = t & 127;
    int h = (t >> 7) & 127;
    int p = (t >> 14) & 1;                         // row parity
    int b = (t >> 15) & 1;

    float qe[NH], qo[NH], ke[NH], ko[NH], ve[NH], vo[NH];
    #pragma unroll
    for (int i = 0; i < NH; i++){ qe[i]=qo[i]=ke[i]=ko[i]=ve[i]=vo[i]=0.f; }

    int rowoff = (2*h + p)*256 + 2*w;
    const float* cp = cur + b*64*65536 + rowoff;
    const float* rp = ref + b*64*65536 + rowoff;

    #pragma unroll 4
    for (int c = 0; c < 64; c++){
        float2 cv = *(const float2*)(cp + c*65536);
        float2 rv = *(const float2*)(rp + c*65536);
        #pragma unroll
        for (int hh = 0; hh < NH; hh++){
            float wq = sW[hh*64 + c];
            qe[hh] += wq*cv.x; qo[hh] += wq*cv.y;
            float wk = sW[512 + hh*64 + c];
            ke[hh] += wk*rv.x; ko[hh] += wk*rv.y;
            float wv = sW[1024 + hh*64 + c];
            ve[hh] += wv*rv.x; vo[hh] += wv*rv.y;
        }
    }

    int se = p ? 3 : 0;          // even column sub
    int so = p ? 1 : 2;          // odd column sub
    int sbe = se*2 + b, sbo = so*2 + b;
    int pix = h*128 + w;
    #pragma unroll
    for (int hh = 0; hh < NH; hh++){
        g_q[(sbe*NH+hh)*SPIX + pix] = qe[hh];
        g_q[(sbo*NH+hh)*SPIX + pix] = qo[hh];
        g_k[(sbe*NH+hh)*SPIX + pix] = ke[hh];
        g_k[(sbo*NH+hh)*SPIX + pix] = ko[hh];
        g_v[(sbe*NH+hh)*SPIX + pix] = ve[hh];
        g_v[(sbo*NH+hh)*SPIX + pix] = vo[hh];
    }
}

// ---------------------------------------------------------------------------
// Kernel 2: axial attention (both directions) + head combine -> flow maps.
// Block = (sb, dir, group of 8 lines). Heads looped in-block, so each flow
// element is written exactly once (no atomics, no zero-init).
// dir 0 = horizontal (line = row h, attend over columns)  -> g_fx
// dir 1 = vertical   (line = col w, attend over rows)     -> g_fy
// Rank-1 scores: softmax_l(q * k_l); |scores| small so no max-subtraction.
// ---------------------------------------------------------------------------
__global__ void __launch_bounds__(256) attn_kernel(
    const float* __restrict__ Wver, const float* __restrict__ Whor)
{
    __shared__ float ks[SHW*9], vs[SHW*9];   // [pos][8 lines], stride 9 pad
    int tid = threadIdx.x;
    int l0  = blockIdx.x * 8;    // 16 groups
    int dir = blockIdx.y;        // 2
    int sb  = blockIdx.z;        // 8
    const float* Wd = dir ? Wver : Whor;

    int lineL[4], pos[4];
    #pragma unroll
    for (int j = 0; j < 4; j++){
        int oe = tid + j*256;
        if (dir == 0){ lineL[j] = oe >> 7; pos[j] = oe & 127; }
        else         { lineL[j] = oe & 7;  pos[j] = oe >> 3;  }
    }
    float out[4] = {0.f,0.f,0.f,0.f};

    for (int hh = 0; hh < NH; hh++){
        const float* qb = g_q + (sb*NH+hh)*SPIX;
        const float* kb = g_k + (sb*NH+hh)*SPIX;
        const float* vb = g_v + (sb*NH+hh)*SPIX;

        __syncthreads();   // guard smem reuse from previous head
        #pragma unroll
        for (int i0 = 0; i0 < 4; i0++){
            int i = tid + i0*256;
            int ll, pp, goff;
            if (dir == 0){ ll = i >> 7; pp = i & 127; goff = l0*128 + i; }
            else         { ll = i & 7;  pp = i >> 3;  goff = pp*128 + l0 + ll; }
            ks[pp*9 + ll] = kb[goff];
            vs[pp*9 + ll] = vb[goff];
        }
        __syncthreads();

        float qln[4], acc[4] = {0.f,0.f,0.f,0.f}, den[4] = {0.f,0.f,0.f,0.f};
        #pragma unroll
        for (int j = 0; j < 4; j++){
            int qoff = (dir == 0) ? (l0 + lineL[j])*128 + pos[j]
                                  : pos[j]*128 + l0 + lineL[j];
            qln[j] = qb[qoff] * 1.4426950408889634f;   // log2(e)
        }
        for (int l = 0; l < SHW; l++){
            #pragma unroll
            for (int j = 0; j < 4; j++){
                float kl = ks[l*9 + lineL[j]];
                float e  = ex2(qln[j]*kl);
                acc[j] += e * vs[l*9 + lineL[j]];
                den[j] += e;
            }
        }
        float wgt = Wd[hh];
        #pragma unroll
        for (int j = 0; j < 4; j++)
            out[j] += wgt * __fdividef(acc[j], den[j]);
    }

    float* fp = dir ? g_fy : g_fx;
    #pragma unroll
    for (int j = 0; j < 4; j++){
        int addr = (dir == 0) ? sb*SPIX + (l0 + lineL[j])*128 + pos[j]
                              : sb*SPIX + pos[j]*128 + l0 + lineL[j];
        fp[addr] = out[j];
    }
}

// ---------------------------------------------------------------------------
// Kernel 3: bilinear border grid-sample of ref sub-images + interleave to
// the full-res output. ix = wx + fx, iy = hy + fy (exact collapse of the
// normalized-grid math). One thread per output element, coalesced writes.
// ---------------------------------------------------------------------------
__global__ void __launch_bounds__(256) warp_kernel(
    const float* __restrict__ ref, float* __restrict__ out)
{
    int t = blockIdx.x*256 + threadIdx.x;    // 8388608 total
    int w  = t & 255;
    int h  = (t >> 8) & 255;
    int bc = t >> 16;                        // b*64 + c
    int b  = bc >> 6;
    int dy = h & 1, dx = w & 1;
    int s  = dy ? (dx ? 1 : 3) : (dx ? 2 : 0);
    int sb = s*2 + b;
    int hy = h >> 1, wx = w >> 1;
    int fo = sb*SPIX + hy*128 + wx;

    float ix = (float)wx + g_fx[fo];
    float iy = (float)hy + g_fy[fo];
    float x0f = floorf(ix), y0f = floorf(iy);
    float fx = ix - x0f,  fy = iy - y0f;
    int x0 = (int)x0f, y0 = (int)y0f;
    int x0c = min(max(x0,   0), 127), x1c = min(max(x0+1, 0), 127);
    int y0c = min(max(y0,   0), 127), y1c = min(max(y0+1, 0), 127);

    const float* rp = ref + bc*65536 + dy*256 + dx;   // fold sub offsets in
    float v00 = rp[(y0c*256 + x0c)*2];
    float v01 = rp[(y0c*256 + x1c)*2];
    float v10 = rp[(y1c*256 + x0c)*2];
    float v11 = rp[(y1c*256 + x1c)*2];

    float wx0 = 1.f - fx, wy0 = 1.f - fy;
    out[t] = (v00*wx0 + v01*fx)*wy0 + (v10*wx0 + v11*fx)*fy;
}

// ---------------------------------------------------------------------------
extern "C" void kernel_launch(void* const* d_in, const int* in_sizes, int n_in,
                              void* d_out, int out_size)
{
    const float* cur  = (const float*)d_in[0];
    const float* ref  = (const float*)d_in[1];
    const float* Wq   = (const float*)d_in[2];
    const float* Wk   = (const float*)d_in[3];
    const float* Wv   = (const float*)d_in[4];
    const float* Wver = (const float*)d_in[5];
    const float* Whor = (const float*)d_in[6];
    float* out = (float*)d_out;

    qkv_kernel<<<256, 256>>>(cur, ref, Wq, Wk, Wv);
    attn_kernel<<<dim3(16, 2, 8), 256>>>(Wver, Whor);
    warp_kernel<<<32768, 256>>>(ref, out);
}

// round 5
// speedup vs baseline: 1.3587x; 1.3587x over previous
#include <cuda_runtime.h>

#define NSB 8          // 4 quadrants * B=2
#define NH 8           // heads
#define SHW 128        // sub image H=W
#define SPIX (SHW*SHW) // 16384

// scratch (device globals: allocation-free)
__device__ float g_q[NSB*NH*SPIX];
__device__ float g_k[NSB*NH*SPIX];
__device__ float g_v[NSB*NH*SPIX];
__device__ float g_fx[NSB*SPIX];   // horizontal flow (pixel units)
__device__ float g_fy[NSB*SPIX];   // vertical flow

// ---------------------------------------------------------------------------
// Kernel 1: fused q/k/v 1x1-conv projection. One thread = one sub-pixel,
// 131072 threads / 512 blocks for occupancy. Strided (stride-2) loads are
// L2-resident; the other parity is consumed by sibling blocks.
// sub order: 0=ul(0,0) 1=br(1,1) 2=ur(0,1) 3=bl(1,0); sb = s*2 + b
// ---------------------------------------------------------------------------
__global__ void __launch_bounds__(256) qkv_kernel(
    const float* __restrict__ cur, const float* __restrict__ ref,
    const float* __restrict__ Wq, const float* __restrict__ Wk,
    const float* __restrict__ Wv)
{
    __shared__ float sW[1536];   // Wq | Wk | Wv, each [8][64]
    for (int i = threadIdx.x; i < 1536; i += 256)
        sW[i] = (i < 512) ? Wq[i] : (i < 1024 ? Wk[i-512] : Wv[i-1024]);
    __syncthreads();

    int t = blockIdx.x*256 + threadIdx.x;          // 131072 threads
    int w = t & 127;
    int h = (t >> 7) & 127;
    int s = (t >> 14) & 3;
    int b = (t >> 16) & 1;
    int py = s & 1;                    // s in {1,3}
    int px = (s == 1 || s == 2) ? 1 : 0;

    float qa[NH], ka[NH], va[NH];
    #pragma unroll
    for (int i = 0; i < NH; i++){ qa[i]=ka[i]=va[i]=0.f; }

    int off = (2*h + py)*256 + (2*w + px);
    const float* cp = cur + b*64*65536 + off;
    const float* rp = ref + b*64*65536 + off;

    #pragma unroll 4
    for (int c = 0; c < 64; c++){
        float cv = __ldg(cp + c*65536);
        float rv = __ldg(rp + c*65536);
        #pragma unroll
        for (int hh = 0; hh < NH; hh++){
            qa[hh] += sW[hh*64 + c]*cv;
            ka[hh] += sW[512 + hh*64 + c]*rv;
            va[hh] += sW[1024 + hh*64 + c]*rv;
        }
    }

    int sb  = s*2 + b;
    int pix = h*128 + w;
    #pragma unroll
    for (int hh = 0; hh < NH; hh++){
        g_q[(sb*NH+hh)*SPIX + pix] = qa[hh];
        g_k[(sb*NH+hh)*SPIX + pix] = ka[hh];
        g_v[(sb*NH+hh)*SPIX + pix] = va[hh];
    }
}

// ---------------------------------------------------------------------------
// Kernel 2: axial attention via Taylor-moment expansion (NO exp/MUFU).
//   sum_l exp(q k_l) v_l = sum_n q^n * [ (sum_l v_l k_l^n) / n! ]
// Per (line, head): 17 numerator + 17 denominator coefficients, then each
// query is two deg-16 Horner evaluations. Exact in k; truncation error
// bounded by x^17/17! at |x|<=~5.3 -> ~1e-5 relative on the flow.
//
// Block: (4-line group, dir, sb), 256 threads, heads staged 4 at a time.
// dir 0 = horizontal (line = row, attend over cols)  -> g_fx  (Whor)
// dir 1 = vertical   (line = col, attend over rows)  -> g_fy  (Wver)
// ---------------------------------------------------------------------------
#define NT 17          // Taylor terms (deg 0..16)
#define SSTR 144       // smem row stride (conflict-free for moment reads)

__global__ void __launch_bounds__(256) attn_kernel(
    const float* __restrict__ Wver, const float* __restrict__ Whor)
{
    __shared__ float ks[16*SSTR], vs[16*SSTR];   // 16 (head,line) pairs x 128 keys
    __shared__ float sc[16*NT], sd[16*NT];       // scaled moment coefficients

    const float invf[NT] = {
        1.0f, 1.0f, 0.5f, 1.6666666666666666e-1f, 4.1666666666666664e-2f,
        8.3333333333333332e-3f, 1.3888888888888889e-3f, 1.9841269841269841e-4f,
        2.4801587301587301e-5f, 2.7557319223985893e-6f, 2.7557319223985888e-7f,
        2.5052108385441720e-8f, 2.0876756987868100e-9f, 1.6059043836821613e-10f,
        1.1470745597729725e-11f, 7.6471637318198164e-13f, 4.7794773323873853e-14f };

    int tid = threadIdx.x;
    int l0  = blockIdx.x * 4;    // 32 groups of 4 lines
    int dir = blockIdx.y;        // 2
    int sb  = blockIdx.z;        // 8
    const float* Wd = dir ? Wver : Whor;

    int warp = tid >> 5, lane = tid & 31;
    float out[2] = {0.f, 0.f};

    for (int hg = 0; hg < 2; hg++){               // head-half passes
        __syncthreads();   // previous pass done with sc/sd + smem
        // ---- stage k,v for 4 heads x 4 lines ----
        #pragma unroll
        for (int it = 0; it < 8; it++){
            int idx = tid + it*256;               // 0..2047
            int hh  = idx >> 9;                   // local head 0..3
            int rem = idx & 511;
            int ll, l;
            if (dir == 0){ ll = rem >> 7; l = rem & 127; }
            else         { ll = rem & 3;  l = rem >> 2;  }
            int goff = (dir == 0) ? (l0+ll)*128 + l : l*128 + l0 + ll;
            int gb   = (sb*NH + hg*4 + hh)*SPIX;
            int sa   = (hh*4 + ll)*SSTR + l;
            ks[sa] = g_k[gb + goff];
            vs[sa] = g_v[gb + goff];
        }
        __syncthreads();

        // ---- moments: warp covers 2 pairs, 16 lanes/pair, 8 keys/lane ----
        {
            int p   = 2*warp + (lane >> 4);       // pair 0..15
            int sub = lane & 15;
            float c[NT], d[NT];
            #pragma unroll
            for (int n = 0; n < NT; n++){ c[n]=0.f; d[n]=0.f; }
            const float* kp = ks + p*SSTR;
            const float* vp = vs + p*SSTR;
            #pragma unroll 2
            for (int i = 0; i < 8; i++){
                int l = sub + 16*i;
                float k = kp[l], v = vp[l];
                float u = 1.f;
                #pragma unroll
                for (int n = 0; n < NT; n++){
                    d[n] += u; c[n] += v*u; u *= k;
                }
            }
            #pragma unroll
            for (int n = 0; n < NT; n++){
                #pragma unroll
                for (int off = 1; off <= 8; off <<= 1){
                    c[n] += __shfl_xor_sync(0xffffffffu, c[n], off);
                    d[n] += __shfl_xor_sync(0xffffffffu, d[n], off);
                }
            }
            if (sub == 0){
                #pragma unroll
                for (int n = 0; n < NT; n++){
                    sc[p*NT + n] = c[n]*invf[n];
                    sd[p*NT + n] = d[n]*invf[n];
                }
            }
        }
        __syncthreads();

        // ---- eval: 2048 queries, 8 per thread (2 pixels x 4 heads) ----
        #pragma unroll
        for (int i = 0; i < 8; i++){
            int idx = tid + i*256;
            int hh  = idx >> 9;
            int rem = idx & 511;
            int ll, qq;
            if (dir == 0){ ll = rem >> 7; qq = rem & 127; }
            else         { ll = rem & 3;  qq = rem >> 2;  }
            int p   = hh*4 + ll;
            int pix = (dir == 0) ? (l0+ll)*128 + qq : qq*128 + l0 + ll;
            float x = g_q[(sb*NH + hg*4 + hh)*SPIX + pix];
            const float* cp = sc + p*NT;
            const float* dp = sd + p*NT;
            float num = cp[NT-1], den = dp[NT-1];
            #pragma unroll
            for (int n = NT-2; n >= 0; n--){
                num = fmaf(num, x, cp[n]);
                den = fmaf(den, x, dp[n]);
            }
            out[i & 1] += __ldg(Wd + hg*4 + hh) * __fdividef(num, den);
        }
    }

    // ---- write flows ----
    float* fp = dir ? g_fy : g_fx;
    #pragma unroll
    for (int j = 0; j < 2; j++){
        int rem = tid + j*256;
        int ll, qq;
        if (dir == 0){ ll = rem >> 7; qq = rem & 127; }
        else         { ll = rem & 3;  qq = rem >> 2;  }
        int pix = (dir == 0) ? (l0+ll)*128 + qq : qq*128 + l0 + ll;
        fp[sb*SPIX + pix] = out[j];
    }
}

// ---------------------------------------------------------------------------
// Kernel 3: bilinear border grid-sample + interleave (ix = wx+fx, iy = hy+fy)
// ---------------------------------------------------------------------------
__global__ void __launch_bounds__(256) warp_kernel(
    const float* __restrict__ ref, float* __restrict__ out)
{
    int t = blockIdx.x*256 + threadIdx.x;    // 8388608 total
    int w  = t & 255;
    int h  = (t >> 8) & 255;
    int bc = t >> 16;                        // b*64 + c
    int b  = bc >> 6;
    int dy = h & 1, dx = w & 1;
    int s  = dy ? (dx ? 1 : 3) : (dx ? 2 : 0);
    int sb = s*2 + b;
    int hy = h >> 1, wx = w >> 1;
    int fo = sb*SPIX + hy*128 + wx;

    float ix = (float)wx + g_fx[fo];
    float iy = (float)hy + g_fy[fo];
    float x0f = floorf(ix), y0f = floorf(iy);
    float fx = ix - x0f,  fy = iy - y0f;
    int x0 = (int)x0f, y0 = (int)y0f;
    int x0c = min(max(x0,   0), 127), x1c = min(max(x0+1, 0), 127);
    int y0c = min(max(y0,   0), 127), y1c = min(max(y0+1, 0), 127);

    const float* rp = ref + bc*65536 + dy*256 + dx;   // fold sub offsets in
    float v00 = rp[(y0c*256 + x0c)*2];
    float v01 = rp[(y0c*256 + x1c)*2];
    float v10 = rp[(y1c*256 + x0c)*2];
    float v11 = rp[(y1c*256 + x1c)*2];

    float wx0 = 1.f - fx, wy0 = 1.f - fy;
    out[t] = (v00*wx0 + v01*fx)*wy0 + (v10*wx0 + v11*fx)*fy;
}

// ---------------------------------------------------------------------------
extern "C" void kernel_launch(void* const* d_in, const int* in_sizes, int n_in,
                              void* d_out, int out_size)
{
    const float* cur  = (const float*)d_in[0];
    const float* ref  = (const float*)d_in[1];
    const float* Wq   = (const float*)d_in[2];
    const float* Wk   = (const float*)d_in[3];
    const float* Wv   = (const float*)d_in[4];
    const float* Wver = (const float*)d_in[5];
    const float* Whor = (const float*)d_in[6];
    float* out = (float*)d_out;

    qkv_kernel<<<512, 256>>>(cur, ref, Wq, Wk, Wv);
    attn_kernel<<<dim3(32, 2, 8), 256>>>(Wver, Whor);
    warp_kernel<<<32768, 256>>>(ref, out);
}

// round 9
// speedup vs baseline: 1.4518x; 1.0685x over previous
#include <cuda_runtime.h>

#define NSB 8          // 4 quadrants * B=2
#define NH 8           // heads
#define SHW 128        // sub image H=W
#define SPIX (SHW*SHW) // 16384

// scratch (device globals: allocation-free)
__device__ float g_q[NSB*NH*SPIX];
__device__ float g_k[NSB*NH*SPIX];
__device__ float g_v[NSB*NH*SPIX];
__device__ float g_fx[NSB*SPIX];   // horizontal flow (pixel units)
__device__ float g_fy[NSB*SPIX];   // vertical flow

// ---------------------------------------------------------------------------
// Kernel 1: fused q/k/v 1x1-conv projection, FULL-RES pixel per thread.
// Loads are perfectly coalesced (consecutive w across lanes); the sub-image
// split is applied only at the store. 131072 threads / 1024 blocks of 128;
// launch_bounds(128,8) caps regs at 64 -> ~8 blocks/SM residency.
// sub order: 0=ul(0,0) 1=br(1,1) 2=ur(0,1) 3=bl(1,0); sb = s*2 + b
// ---------------------------------------------------------------------------
__global__ void __launch_bounds__(128, 8) qkv_kernel(
    const float* __restrict__ cur, const float* __restrict__ ref,
    const float* __restrict__ Wq, const float* __restrict__ Wk,
    const float* __restrict__ Wv)
{
    __shared__ float sW[1536];   // Wq | Wk | Wv, each [8][64]
    for (int i = threadIdx.x; i < 1536; i += 128)
        sW[i] = (i < 512) ? Wq[i] : (i < 1024 ? Wk[i-512] : Wv[i-1024]);
    __syncthreads();

    int t = blockIdx.x*128 + threadIdx.x;   // 131072 threads, full-res pixels
    int w = t & 255;
    int h = (t >> 8) & 255;
    int b = t >> 16;

    const float* cp = cur + b*64*65536 + h*256 + w;
    const float* rp = ref + b*64*65536 + h*256 + w;

    float qa[NH], ka[NH], va[NH];
    #pragma unroll
    for (int i = 0; i < NH; i++){ qa[i]=ka[i]=va[i]=0.f; }

    #pragma unroll 4
    for (int c = 0; c < 64; c++){
        float cv = cp[c*65536];
        float rv = rp[c*65536];
        #pragma unroll
        for (int hh = 0; hh < NH; hh++){
            qa[hh] += sW[hh*64 + c]*cv;
            ka[hh] += sW[512 + hh*64 + c]*rv;
            va[hh] += sW[1024 + hh*64 + c]*rv;
        }
    }

    int dy = h & 1, dx = w & 1;
    int s  = dy ? (dx ? 1 : 3) : (dx ? 2 : 0);
    int sb = s*2 + b;
    int pix = (h >> 1)*128 + (w >> 1);
    #pragma unroll
    for (int hh = 0; hh < NH; hh++){
        g_q[(sb*NH+hh)*SPIX + pix] = qa[hh];
        g_k[(sb*NH+hh)*SPIX + pix] = ka[hh];
        g_v[(sb*NH+hh)*SPIX + pix] = va[hh];
    }
}

// ---------------------------------------------------------------------------
// Kernel 2: axial attention via Taylor-moment expansion (NO exp/MUFU).
//   sum_l exp(q k_l) v_l = sum_n q^n * [ (sum_l v_l k_l^n) / n! ]
// Per (line, head): 17 numerator + 17 denominator coefficients, then each
// query is two deg-16 Horner evaluations. Exact in k; truncation error
// bounded by x^17/17! at |x|<=~5.3 -> ~1e-5 relative on the flow.
//
// Block: (4-line group, dir, sb), 256 threads, heads staged 4 at a time.
// dir 0 = horizontal (line = row, attend over cols)  -> g_fx  (Whor)
// dir 1 = vertical   (line = col, attend over rows)  -> g_fy  (Wver)
// ---------------------------------------------------------------------------
#define NT 17          // Taylor terms (deg 0..16)
#define SSTR 144       // smem row stride (conflict-free for moment reads)

__global__ void __launch_bounds__(256) attn_kernel(
    const float* __restrict__ Wver, const float* __restrict__ Whor)
{
    __shared__ float ks[16*SSTR], vs[16*SSTR];   // 16 (head,line) pairs x 128 keys
    __shared__ float sc[16*NT], sd[16*NT];       // scaled moment coefficients

    const float invf[NT] = {
        1.0f, 1.0f, 0.5f, 1.6666666666666666e-1f, 4.1666666666666664e-2f,
        8.3333333333333332e-3f, 1.3888888888888889e-3f, 1.9841269841269841e-4f,
        2.4801587301587301e-5f, 2.7557319223985893e-6f, 2.7557319223985888e-7f,
        2.5052108385441720e-8f, 2.0876756987868100e-9f, 1.6059043836821613e-10f,
        1.1470745597729725e-11f, 7.6471637318198164e-13f, 4.7794773323873853e-14f };

    int tid = threadIdx.x;
    int l0  = blockIdx.x * 4;    // 32 groups of 4 lines
    int dir = blockIdx.y;        // 2
    int sb  = blockIdx.z;        // 8
    const float* Wd = dir ? Wver : Whor;

    int warp = tid >> 5, lane = tid & 31;
    float out[2] = {0.f, 0.f};

    for (int hg = 0; hg < 2; hg++){               // head-half passes
        __syncthreads();   // previous pass done with sc/sd + smem
        // ---- stage k,v for 4 heads x 4 lines ----
        #pragma unroll
        for (int it = 0; it < 8; it++){
            int idx = tid + it*256;               // 0..2047
            int hh  = idx >> 9;                   // local head 0..3
            int rem = idx & 511;
            int ll, l;
            if (dir == 0){ ll = rem >> 7; l = rem & 127; }
            else         { ll = rem & 3;  l = rem >> 2;  }
            int goff = (dir == 0) ? (l0+ll)*128 + l : l*128 + l0 + ll;
            int gb   = (sb*NH + hg*4 + hh)*SPIX;
            int sa   = (hh*4 + ll)*SSTR + l;
            ks[sa] = g_k[gb + goff];
            vs[sa] = g_v[gb + goff];
        }
        __syncthreads();

        // ---- moments: warp covers 2 pairs, 16 lanes/pair, 8 keys/lane ----
        {
            int p   = 2*warp + (lane >> 4);       // pair 0..15
            int sub = lane & 15;
            float c[NT], d[NT];
            #pragma unroll
            for (int n = 0; n < NT; n++){ c[n]=0.f; d[n]=0.f; }
            const float* kp = ks + p*SSTR;
            const float* vp = vs + p*SSTR;
            #pragma unroll 2
            for (int i = 0; i < 8; i++){
                int l = sub + 16*i;
                float k = kp[l], v = vp[l];
                float u = 1.f;
                #pragma unroll
                for (int n = 0; n < NT; n++){
                    d[n] += u; c[n] += v*u; u *= k;
                }
            }
            #pragma unroll
            for (int n = 0; n < NT; n++){
                #pragma unroll
                for (int off = 1; off <= 8; off <<= 1){
                    c[n] += __shfl_xor_sync(0xffffffffu, c[n], off);
                    d[n] += __shfl_xor_sync(0xffffffffu, d[n], off);
                }
            }
            if (sub == 0){
                #pragma unroll
                for (int n = 0; n < NT; n++){
                    sc[p*NT + n] = c[n]*invf[n];
                    sd[p*NT + n] = d[n]*invf[n];
                }
            }
        }
        __syncthreads();

        // ---- eval: 2048 queries, 8 per thread (2 pixels x 4 heads) ----
        #pragma unroll
        for (int i = 0; i < 8; i++){
            int idx = tid + i*256;
            int hh  = idx >> 9;
            int rem = idx & 511;
            int ll, qq;
            if (dir == 0){ ll = rem >> 7; qq = rem & 127; }
            else         { ll = rem & 3;  qq = rem >> 2;  }
            int p   = hh*4 + ll;
            int pix = (dir == 0) ? (l0+ll)*128 + qq : qq*128 + l0 + ll;
            float x = g_q[(sb*NH + hg*4 + hh)*SPIX + pix];
            const float* cp = sc + p*NT;
            const float* dp = sd + p*NT;
            float num = cp[NT-1], den = dp[NT-1];
            #pragma unroll
            for (int n = NT-2; n >= 0; n--){
                num = fmaf(num, x, cp[n]);
                den = fmaf(den, x, dp[n]);
            }
            out[i & 1] += __ldg(Wd + hg*4 + hh) * __fdividef(num, den);
        }
    }

    // ---- write flows ----
    float* fp = dir ? g_fy : g_fx;
    #pragma unroll
    for (int j = 0; j < 2; j++){
        int rem = tid + j*256;
        int ll, qq;
        if (dir == 0){ ll = rem >> 7; qq = rem & 127; }
        else         { ll = rem & 3;  qq = rem >> 2;  }
        int pix = (dir == 0) ? (l0+ll)*128 + qq : qq*128 + l0 + ll;
        fp[sb*SPIX + pix] = out[j];
    }
}

// ---------------------------------------------------------------------------
// Kernel 3: bilinear border grid-sample + interleave (ix = wx+fx, iy = hy+fy)
// ---------------------------------------------------------------------------
__global__ void __launch_bounds__(256) warp_kernel(
    const float* __restrict__ ref, float* __restrict__ out)
{
    int t = blockIdx.x*256 + threadIdx.x;    // 8388608 total
    int w  = t & 255;
    int h  = (t >> 8) & 255;
    int bc = t >> 16;                        // b*64 + c
    int b  = bc >> 6;
    int dy = h & 1, dx = w & 1;
    int s  = dy ? (dx ? 1 : 3) : (dx ? 2 : 0);
    int sb = s*2 + b;
    int hy = h >> 1, wx = w >> 1;
    int fo = sb*SPIX + hy*128 + wx;

    float ix = (float)wx + g_fx[fo];
    float iy = (float)hy + g_fy[fo];
    float x0f = floorf(ix), y0f = floorf(iy);
    float fx = ix - x0f,  fy = iy - y0f;
    int x0 = (int)x0f, y0 = (int)y0f;
    int x0c = min(max(x0,   0), 127), x1c = min(max(x0+1, 0), 127);
    int y0c = min(max(y0,   0), 127), y1c = min(max(y0+1, 0), 127);

    const float* rp = ref + bc*65536 + dy*256 + dx;   // fold sub offsets in
    float v00 = rp[(y0c*256 + x0c)*2];
    float v01 = rp[(y0c*256 + x1c)*2];
    float v10 = rp[(y1c*256 + x0c)*2];
    float v11 = rp[(y1c*256 + x1c)*2];

    float wx0 = 1.f - fx, wy0 = 1.f - fy;
    out[t] = (v00*wx0 + v01*fx)*wy0 + (v10*wx0 + v11*fx)*fy;
}

// ---------------------------------------------------------------------------
extern "C" void kernel_launch(void* const* d_in, const int* in_sizes, int n_in,
                              void* d_out, int out_size)
{
    const float* cur  = (const float*)d_in[0];
    const float* ref  = (const float*)d_in[1];
    const float* Wq   = (const float*)d_in[2];
    const float* Wk   = (const float*)d_in[3];
    const float* Wv   = (const float*)d_in[4];
    const float* Wver = (const float*)d_in[5];
    const float* Whor = (const float*)d_in[6];
    float* out = (float*)d_out;

    qkv_kernel<<<1024, 128>>>(cur, ref, Wq, Wk, Wv);
    attn_kernel<<<dim3(32, 2, 8), 256>>>(Wver, Whor);
    warp_kernel<<<32768, 256>>>(ref, out);
}

// round 14
// speedup vs baseline: 1.5777x; 1.0867x over previous
#include <cuda_runtime.h>

#define NSB 8          // 4 quadrants * B=2
#define NH 8           // heads
#define SHW 128        // sub image H=W
#define SPIX (SHW*SHW) // 16384

// scratch (device globals: allocation-free)
__device__ float g_q[NSB*NH*SPIX];
__device__ float g_k[NSB*NH*SPIX];
__device__ float g_v[NSB*NH*SPIX];
__device__ float g_fx[NSB*SPIX];   // horizontal flow (pixel units)
__device__ float g_fy[NSB*SPIX];   // vertical flow

// packed f32x2 fma: d = a*b + c on both 32-bit halves (SASS FFMA2)
__device__ __forceinline__ unsigned long long fma2(
    unsigned long long a, unsigned long long b, unsigned long long c){
    unsigned long long d;
    asm("fma.rn.f32x2 %0, %1, %2, %3;" : "=l"(d) : "l"(a), "l"(b), "l"(c));
    return d;
}

// ---------------------------------------------------------------------------
// Kernel 1: fused q/k/v 1x1-conv projection with packed f32x2 math.
// One thread = one HORIZONTAL PIXEL PAIR (full-res), so every channel needs
// just one LDG.64 from cur + one from ref, and 24 FFMA2 (48 MACs). Weights
// live in smem pre-duplicated as (w,w) 64-bit words -> one broadcast LDS.64
// feeds one FFMA2. Even/odd pixels of the pair belong to different subs;
// stores stay coalesced per parity.
// sub order: 0=ul(0,0) 1=br(1,1) 2=ur(0,1) 3=bl(1,0); sb = s*2 + b
// ---------------------------------------------------------------------------
__global__ void __launch_bounds__(128, 6) qkv_kernel(
    const float* __restrict__ cur, const float* __restrict__ ref,
    const float* __restrict__ Wq, const float* __restrict__ Wk,
    const float* __restrict__ Wv)
{
    __shared__ unsigned long long sW2[64*24];   // [c][j] packed (w,w); 12KB
    for (int i = threadIdx.x; i < 64*24; i += 128){
        int c = i / 24, j = i % 24;
        float w = (j < 8) ? Wq[j*64 + c]
                : (j < 16 ? Wk[(j-8)*64 + c] : Wv[(j-16)*64 + c]);
        unsigned long long p = (unsigned long long)__float_as_uint(w);
        sW2[i] = p | (p << 32);
    }
    __syncthreads();

    int t  = blockIdx.x*128 + threadIdx.x;   // 65536 threads, 2 px each
    int w2 = t & 127;                        // pixel pair: cols 2*w2, 2*w2+1
    int h  = (t >> 7) & 255;
    int b  = t >> 15;

    const unsigned long long* cp =
        (const unsigned long long*)(cur + (size_t)b*64*65536 + h*256) + w2;
    const unsigned long long* rp =
        (const unsigned long long*)(ref + (size_t)b*64*65536 + h*256) + w2;

    unsigned long long acc[24];
    #pragma unroll
    for (int j = 0; j < 24; j++) acc[j] = 0ull;

    #pragma unroll 4
    for (int c = 0; c < 64; c++){
        unsigned long long cv = cp[c*32768];   // 65536 floats = 32768 u64
        unsigned long long rv = rp[c*32768];
        const unsigned long long* wc = sW2 + c*24;
        #pragma unroll
        for (int j = 0; j < 8; j++)  acc[j]    = fma2(wc[j],    cv, acc[j]);
        #pragma unroll
        for (int j = 8; j < 24; j++) acc[j]    = fma2(wc[j],    rv, acc[j]);
    }

    int dy  = h & 1;
    int se  = dy ? 3 : 0;            // dx=0 sub
    int so  = dy ? 1 : 2;            // dx=1 sub
    int sbe = se*2 + b, sbo = so*2 + b;
    int pix = (h >> 1)*128 + w2;

    #pragma unroll
    for (int hh = 0; hh < NH; hh++){
        float qlo = __uint_as_float((unsigned)acc[hh]);
        float qhi = __uint_as_float((unsigned)(acc[hh] >> 32));
        float klo = __uint_as_float((unsigned)acc[8+hh]);
        float khi = __uint_as_float((unsigned)(acc[8+hh] >> 32));
        float vlo = __uint_as_float((unsigned)acc[16+hh]);
        float vhi = __uint_as_float((unsigned)(acc[16+hh] >> 32));
        g_q[(sbe*NH+hh)*SPIX + pix] = qlo;
        g_q[(sbo*NH+hh)*SPIX + pix] = qhi;
        g_k[(sbe*NH+hh)*SPIX + pix] = klo;
        g_k[(sbo*NH+hh)*SPIX + pix] = khi;
        g_v[(sbe*NH+hh)*SPIX + pix] = vlo;
        g_v[(sbo*NH+hh)*SPIX + pix] = vhi;
    }
}

// ---------------------------------------------------------------------------
// Kernel 2: axial attention via Taylor-moment expansion (NO exp/MUFU).
//   sum_l exp(q k_l) v_l = sum_n q^n * [ (sum_l v_l k_l^n) / n! ]
// Per (line, head): 17 numerator + 17 denominator coefficients, then each
// query is two deg-16 Horner evaluations. Exact in k; truncation error
// bounded by x^17/17! at |x|<=~5.3 -> ~1e-5 relative on the flow.
//
// Block: (4-line group, dir, sb), 256 threads, heads staged 4 at a time.
// dir 0 = horizontal (line = row, attend over cols)  -> g_fx  (Whor)
// dir 1 = vertical   (line = col, attend over rows)  -> g_fy  (Wver)
// ---------------------------------------------------------------------------
#define NT 17          // Taylor terms (deg 0..16)
#define SSTR 144       // smem row stride (conflict-free for moment reads)

__global__ void __launch_bounds__(256) attn_kernel(
    const float* __restrict__ Wver, const float* __restrict__ Whor)
{
    __shared__ float ks[16*SSTR], vs[16*SSTR];   // 16 (head,line) pairs x 128 keys
    __shared__ float sc[16*NT], sd[16*NT];       // scaled moment coefficients

    const float invf[NT] = {
        1.0f, 1.0f, 0.5f, 1.6666666666666666e-1f, 4.1666666666666664e-2f,
        8.3333333333333332e-3f, 1.3888888888888889e-3f, 1.9841269841269841e-4f,
        2.4801587301587301e-5f, 2.7557319223985893e-6f, 2.7557319223985888e-7f,
        2.5052108385441720e-8f, 2.0876756987868100e-9f, 1.6059043836821613e-10f,
        1.1470745597729725e-11f, 7.6471637318198164e-13f, 4.7794773323873853e-14f };

    int tid = threadIdx.x;
    int l0  = blockIdx.x * 4;    // 32 groups of 4 lines
    int dir = blockIdx.y;        // 2
    int sb  = blockIdx.z;        // 8
    const float* Wd = dir ? Wver : Whor;

    int warp = tid >> 5, lane = tid & 31;
    float out[2] = {0.f, 0.f};

    for (int hg = 0; hg < 2; hg++){               // head-half passes
        __syncthreads();   // previous pass done with sc/sd + smem
        // ---- stage k,v for 4 heads x 4 lines ----
        #pragma unroll
        for (int it = 0; it < 8; it++){
            int idx = tid + it*256;               // 0..2047
            int hh  = idx >> 9;                   // local head 0..3
            int rem = idx & 511;
            int ll, l;
            if (dir == 0){ ll = rem >> 7; l = rem & 127; }
            else         { ll = rem & 3;  l = rem >> 2;  }
            int goff = (dir == 0) ? (l0+ll)*128 + l : l*128 + l0 + ll;
            int gb   = (sb*NH + hg*4 + hh)*SPIX;
            int sa   = (hh*4 + ll)*SSTR + l;
            ks[sa] = g_k[gb + goff];
            vs[sa] = g_v[gb + goff];
        }
        __syncthreads();

        // ---- moments: warp covers 2 pairs, 16 lanes/pair, 8 keys/lane ----
        {
            int p   = 2*warp + (lane >> 4);       // pair 0..15
            int sub = lane & 15;
            float c[NT], d[NT];
            #pragma unroll
            for (int n = 0; n < NT; n++){ c[n]=0.f; d[n]=0.f; }
            const float* kp = ks + p*SSTR;
            const float* vp = vs + p*SSTR;
            #pragma unroll 2
            for (int i = 0; i < 8; i++){
                int l = sub + 16*i;
                float k = kp[l], v = vp[l];
                float u = 1.f;
                #pragma unroll
                for (int n = 0; n < NT; n++){
                    d[n] += u; c[n] += v*u; u *= k;
                }
            }
            #pragma unroll
            for (int n = 0; n < NT; n++){
                #pragma unroll
                for (int off = 1; off <= 8; off <<= 1){
                    c[n] += __shfl_xor_sync(0xffffffffu, c[n], off);
                    d[n] += __shfl_xor_sync(0xffffffffu, d[n], off);
                }
            }
            if (sub == 0){
                #pragma unroll
                for (int n = 0; n < NT; n++){
                    sc[p*NT + n] = c[n]*invf[n];
                    sd[p*NT + n] = d[n]*invf[n];
                }
            }
        }
        __syncthreads();

        // ---- eval: 2048 queries, 8 per thread (2 pixels x 4 heads) ----
        #pragma unroll
        for (int i = 0; i < 8; i++){
            int idx = tid + i*256;
            int hh  = idx >> 9;
            int rem = idx & 511;
            int ll, qq;
            if (dir == 0){ ll = rem >> 7; qq = rem & 127; }
            else         { ll = rem & 3;  qq = rem >> 2;  }
            int p   = hh*4 + ll;
            int pix = (dir == 0) ? (l0+ll)*128 + qq : qq*128 + l0 + ll;
            float x = g_q[(sb*NH + hg*4 + hh)*SPIX + pix];
            const float* cp = sc + p*NT;
            const float* dp = sd + p*NT;
            float num = cp[NT-1], den = dp[NT-1];
            #pragma unroll
            for (int n = NT-2; n >= 0; n--){
                num = fmaf(num, x, cp[n]);
                den = fmaf(den, x, dp[n]);
            }
            out[i & 1] += __ldg(Wd + hg*4 + hh) * __fdividef(num, den);
        }
    }

    // ---- write flows ----
    float* fp = dir ? g_fy : g_fx;
    #pragma unroll
    for (int j = 0; j < 2; j++){
        int rem = tid + j*256;
        int ll, qq;
        if (dir == 0){ ll = rem >> 7; qq = rem & 127; }
        else         { ll = rem & 3;  qq = rem >> 2;  }
        int pix = (dir == 0) ? (l0+ll)*128 + qq : qq*128 + l0 + ll;
        fp[sb*SPIX + pix] = out[j];
    }
}

// ---------------------------------------------------------------------------
// Kernel 3: bilinear border grid-sample + interleave (ix = wx+fx, iy = hy+fy)
// ---------------------------------------------------------------------------
__global__ void __launch_bounds__(256) warp_kernel(
    const float* __restrict__ ref, float* __restrict__ out)
{
    int t = blockIdx.x*256 + threadIdx.x;    // 8388608 total
    int w  = t & 255;
    int h  = (t >> 8) & 255;
    int bc = t >> 16;                        // b*64 + c
    int b  = bc >> 6;
    int dy = h & 1, dx = w & 1;
    int s  = dy ? (dx ? 1 : 3) : (dx ? 2 : 0);
    int sb = s*2 + b;
    int hy = h >> 1, wx = w >> 1;
    int fo = sb*SPIX + hy*128 + wx;

    float ix = (float)wx + g_fx[fo];
    float iy = (float)hy + g_fy[fo];
    float x0f = floorf(ix), y0f = floorf(iy);
    float fx = ix - x0f,  fy = iy - y0f;
    int x0 = (int)x0f, y0 = (int)y0f;
    int x0c = min(max(x0,   0), 127), x1c = min(max(x0+1, 0), 127);
    int y0c = min(max(y0,   0), 127), y1c = min(max(y0+1, 0), 127);

    const float* rp = ref + bc*65536 + dy*256 + dx;   // fold sub offsets in
    float v00 = rp[(y0c*256 + x0c)*2];
    float v01 = rp[(y0c*256 + x1c)*2];
    float v10 = rp[(y1c*256 + x0c)*2];
    float v11 = rp[(y1c*256 + x1c)*2];

    float wx0 = 1.f - fx, wy0 = 1.f - fy;
    out[t] = (v00*wx0 + v01*fx)*wy0 + (v10*wx0 + v11*fx)*fy;
}

// ---------------------------------------------------------------------------
extern "C" void kernel_launch(void* const* d_in, const int* in_sizes, int n_in,
                              void* d_out, int out_size)
{
    const float* cur  = (const float*)d_in[0];
    const float* ref  = (const float*)d_in[1];
    const float* Wq   = (const float*)d_in[2];
    const float* Wk   = (const float*)d_in[3];
    const float* Wv   = (const float*)d_in[4];
    const float* Wver = (const float*)d_in[5];
    const float* Whor = (const float*)d_in[6];
    float* out = (float*)d_out;

    qkv_kernel<<<512, 128>>>(cur, ref, Wq, Wk, Wv);
    attn_kernel<<<dim3(32, 2, 8), 256>>>(Wver, Whor);
    warp_kernel<<<32768, 256>>>(ref, out);
}